// round 2
// baseline (speedup 1.0000x reference)
#include <cuda_runtime.h>

#define T_  128
#define B_  1024
#define D_  96
#define H_  128
#define BH  (B_ * H_)      // 131072
#define NSL 129            // prefix slices 0..128

#define BETA   0.9f
#define THRESH 0.5f

// Prefix sums over time of C[t] = x_t @ W_in^T.  g_P[k][b][h] = sum_{i<k} C[i][b][h]
__device__ float g_P[(size_t)NSL * BH];   // ~67.6 MB static device global (fits L2-ish)

// ---------------------------------------------------------------------------
// Kernel 1: C = X @ W_in^T  (written into g_P slice t+1; slice 0 stays for 0)
// Block: 64 rows x 128 cols, 512 threads, 4x4 micro-tile (cols strided by 32)
// ---------------------------------------------------------------------------
__global__ void k_gemm_in(const float* __restrict__ x, const float* __restrict__ Win) {
    extern __shared__ float sm[];
    float* Ws = sm;                // [96][129]  Ws[k*129+h] = Win[h][k]  (pad->conflict-free)
    float* As = sm + 96 * 129;     // [64][96]
    const int tid  = threadIdx.x;
    const int row0 = blockIdx.x * 64;

    for (int idx = tid; idx < H_ * D_; idx += 512) {
        int h = idx / D_, k = idx - h * D_;
        Ws[k * 129 + h] = Win[idx];            // coalesced read, conflict-free store
    }
    for (int idx = tid; idx < 64 * D_; idx += 512)
        As[idx] = x[(size_t)row0 * D_ + idx];  // linear copy, coalesced
    __syncthreads();

    const int tx = tid & 31, ty = tid >> 5;
    const int r0 = ty * 4;
    float acc[4][4] = {};
    #pragma unroll 2
    for (int k = 0; k < D_; ++k) {
        float a[4];
        #pragma unroll
        for (int i = 0; i < 4; ++i) a[i] = As[(r0 + i) * 96 + k];   // warp broadcast
        #pragma unroll
        for (int j = 0; j < 4; ++j) {
            float w = Ws[k * 129 + tx + 32 * j];                    // conflict-free
            #pragma unroll
            for (int i = 0; i < 4; ++i) acc[i][j] += a[i] * w;
        }
    }
    #pragma unroll
    for (int i = 0; i < 4; ++i)
        #pragma unroll
        for (int j = 0; j < 4; ++j)
            g_P[(size_t)BH + (size_t)(row0 + r0 + i) * H_ + tx + 32 * j] = acc[i][j];
}

// ---------------------------------------------------------------------------
// Kernel 2: in-place prefix sum over t.  One thread per (b,h).
// ---------------------------------------------------------------------------
__global__ void k_prefix() {
    const size_t tid = (size_t)blockIdx.x * blockDim.x + threadIdx.x;  // 0..BH-1
    float run = 0.f;
    size_t idx = tid;
    g_P[idx] = 0.f;
    #pragma unroll 4
    for (int t = 1; t <= T_; ++t) {
        idx += BH;
        run += g_P[idx];
        g_P[idx] = run;
    }
}

// ---------------------------------------------------------------------------
// Kernel 3: the SNN.  grid = 128 t-values x 16 batch-tiles of 64 rows.
// 512 threads, 4x4 micro-tile, cols strided by 32.  State in registers.
// ---------------------------------------------------------------------------
__global__ void __launch_bounds__(512, 1)
k_snn(const float* __restrict__ Wh0, const float* __restrict__ Wout,
      const float* __restrict__ vx, const float* __restrict__ vy,
      float* __restrict__ out) {
    extern __shared__ float sm[];
    float* Wt     = sm;                      // [128][129]  Wt[k*129+h'] = Wh0[h'][k]
    float* spk    = Wt + 128 * 129;          // [64][128]
    float* WoutS  = spk + 64 * 128;          // [128][2]    WoutS[h*2+o] = Wout[o][h]
    float* memout = WoutS + 256;             // [64][2]

    const int tid = threadIdx.x;
    const int t   = blockIdx.x >> 4;
    const int b0  = (blockIdx.x & 15) * 64;

    for (int idx = tid; idx < H_ * H_; idx += 512) {
        int hp = idx >> 7, k = idx & 127;
        Wt[k * 129 + hp] = Wh0[idx];         // coalesced read, conflict-free store
    }
    if (tid < 256) WoutS[(tid & 127) * 2 + (tid >> 7)] = Wout[tid];
    if (tid < 128) memout[tid] = 0.f;
    __syncthreads();

    const int tx = tid & 31, ty = tid >> 5;
    const int r0 = ty * 4;
    float mem1[4][4] = {};
    float mem2[4][4] = {};

    for (int s = 0; s < 7; ++s) {
        // ---- window bounds (prefix-difference indices), uniform per block ----
        int lo, hi;
        if (t >= 49) {
            lo = t - 49 + 7 * s;
            hi = lo + 7;
        } else {
            int j0 = 7 * s; if (j0 < 1) j0 = 1;
            int j1 = 7 * s + 6; if (j1 > t + 1) j1 = t + 1;
            lo = j0 - 1;
            hi = (j1 >= j0) ? j1 : lo;       // empty window -> acc = 0
        }
        const float* __restrict__ Phi = g_P + (size_t)hi * BH;
        const float* __restrict__ Plo = g_P + (size_t)lo * BH;

        // ---- layer 1: leaky integrate, reset-to-zero, spike ----
        #pragma unroll
        for (int i = 0; i < 4; ++i) {
            const int b = b0 + r0 + i;
            #pragma unroll
            for (int j = 0; j < 4; ++j) {
                const int h = tx + 32 * j;
                float cur = Phi[(size_t)b * H_ + h] - Plo[(size_t)b * H_ + h];
                float m  = mem1[i][j];
                float nm = (m > THRESH) ? 0.f : fmaf(BETA, m, cur);
                mem1[i][j] = nm;
                spk[(r0 + i) * 128 + h] = (nm > THRESH) ? 1.f : 0.f;
            }
        }
        __syncthreads();

        // ---- hidden GEMM: cur2 = spk1 @ Wh0^T  (64x128 @ 128x128 tile) ----
        float acc[4][4] = {};
        #pragma unroll 4
        for (int k = 0; k < 128; ++k) {
            float a[4];
            #pragma unroll
            for (int i = 0; i < 4; ++i) a[i] = spk[(r0 + i) * 128 + k];  // broadcast
            #pragma unroll
            for (int j = 0; j < 4; ++j) {
                float w = Wt[k * 129 + tx + 32 * j];                     // conflict-free
                #pragma unroll
                for (int i = 0; i < 4; ++i) acc[i][j] += a[i] * w;
            }
        }
        __syncthreads();   // before overwriting spk with layer-2 spikes

        // ---- layer 2 ----
        #pragma unroll
        for (int i = 0; i < 4; ++i)
            #pragma unroll
            for (int j = 0; j < 4; ++j) {
                float m  = mem2[i][j];
                float nm = (m > THRESH) ? 0.f : fmaf(BETA, m, acc[i][j]);
                mem2[i][j] = nm;
                spk[(r0 + i) * 128 + tx + 32 * j] = (nm > THRESH) ? 1.f : 0.f;
            }
        __syncthreads();

        // ---- output projection + mem_out accumulate (no reset) ----
        if (tid < 256) {
            const int r = tid >> 2, p = tid & 3;
            float s0 = 0.f, s1 = 0.f;
            #pragma unroll 4
            for (int kk = 0; kk < 32; ++kk) {
                int k = p * 32 + ((kk + tx) & 31);      // lane-rotated -> conflict-free
                float v = spk[r * 128 + k];
                s0 = fmaf(v, WoutS[k * 2 + 0], s0);
                s1 = fmaf(v, WoutS[k * 2 + 1], s1);
            }
            s0 += __shfl_down_sync(0xffffffffu, s0, 2);
            s0 += __shfl_down_sync(0xffffffffu, s0, 1);
            s1 += __shfl_down_sync(0xffffffffu, s1, 2);
            s1 += __shfl_down_sync(0xffffffffu, s1, 1);
            if (p == 0) {
                memout[r * 2 + 0] = fmaf(BETA, memout[r * 2 + 0], s0);
                memout[r * 2 + 1] = fmaf(BETA, memout[r * 2 + 1], s1);
            }
        }
        __syncthreads();   // protect spk + memout before next step
    }

    // ---- epilogue: preds = mem_out * [v_x, v_y] ----
    if (tid < 128) {
        const int r = tid >> 1, o = tid & 1;
        const float v = (o == 0) ? vx[0] : vy[0];
        out[((size_t)t * B_ + b0 + r) * 2 + o] = memout[r * 2 + o] * v;
    }
}

// ---------------------------------------------------------------------------
extern "C" void kernel_launch(void* const* d_in, const int* in_sizes, int n_in,
                              void* d_out, int out_size) {
    const float* x    = (const float*)d_in[0];
    const float* Win  = (const float*)d_in[1];
    const float* Wh0  = (const float*)d_in[2];
    const float* Wout = (const float*)d_in[3];
    const float* vx   = (const float*)d_in[4];
    const float* vy   = (const float*)d_in[5];
    float* out = (float*)d_out;

    const int smem1 = (96 * 129 + 64 * 96) * 4;                 // 74112 B
    const int smem3 = (128 * 129 + 64 * 128 + 256 + 128) * 4;   // 100352 B
    cudaFuncSetAttribute(k_gemm_in, cudaFuncAttributeMaxDynamicSharedMemorySize, smem1);
    cudaFuncSetAttribute(k_snn,     cudaFuncAttributeMaxDynamicSharedMemorySize, smem3);

    k_gemm_in<<<(T_ * B_) / 64, 512, smem1>>>(x, Win);
    k_prefix<<<BH / 256, 256>>>();
    k_snn<<<T_ * 16, 512, smem3>>>(Wh0, Wout, vx, vy, out);
}

// round 3
// speedup vs baseline: 1.0034x; 1.0034x over previous
#include <cuda_runtime.h>

#define T_  128
#define B_  1024
#define D_  96
#define H_  128
#define BH  (B_ * H_)      // 131072
#define NSL 129            // prefix slices 0..128

#define BETA   0.9f
#define THRESH 0.5f

// Prefix sums over time of C[t] = x_t @ W_in^T.  g_P[k][b][h] = sum_{i<k} C[i][b][h]
__device__ float g_P[(size_t)NSL * BH];   // ~67.6 MB static device global (fits L2-ish)

// ---------------------------------------------------------------------------
// Kernel 1: C = X @ W_in^T  (written into g_P slice t+1; slice 0 stays for 0)
// Block: 64 rows x 128 cols, 512 threads, 4x4 micro-tile (cols strided by 32)
// ---------------------------------------------------------------------------
__global__ void k_gemm_in(const float* __restrict__ x, const float* __restrict__ Win) {
    extern __shared__ float sm[];
    float* Ws = sm;                // [96][129]  Ws[k*129+h] = Win[h][k]  (pad->conflict-free)
    float* As = sm + 96 * 129;     // [64][96]
    const int tid  = threadIdx.x;
    const int row0 = blockIdx.x * 64;

    for (int idx = tid; idx < H_ * D_; idx += 512) {
        int h = idx / D_, k = idx - h * D_;
        Ws[k * 129 + h] = Win[idx];            // coalesced read, conflict-free store
    }
    for (int idx = tid; idx < 64 * D_; idx += 512)
        As[idx] = x[(size_t)row0 * D_ + idx];  // linear copy, coalesced
    __syncthreads();

    const int tx = tid & 31, ty = tid >> 5;
    const int r0 = ty * 4;
    float acc[4][4] = {};
    #pragma unroll 2
    for (int k = 0; k < D_; ++k) {
        float a[4];
        #pragma unroll
        for (int i = 0; i < 4; ++i) a[i] = As[(r0 + i) * 96 + k];   // warp broadcast
        #pragma unroll
        for (int j = 0; j < 4; ++j) {
            float w = Ws[k * 129 + tx + 32 * j];                    // conflict-free
            #pragma unroll
            for (int i = 0; i < 4; ++i) acc[i][j] += a[i] * w;
        }
    }
    #pragma unroll
    for (int i = 0; i < 4; ++i)
        #pragma unroll
        for (int j = 0; j < 4; ++j)
            g_P[(size_t)BH + (size_t)(row0 + r0 + i) * H_ + tx + 32 * j] = acc[i][j];
}

// ---------------------------------------------------------------------------
// Kernel 2: in-place prefix sum over t.  One thread per (b,h).
// ---------------------------------------------------------------------------
__global__ void k_prefix() {
    const size_t tid = (size_t)blockIdx.x * blockDim.x + threadIdx.x;  // 0..BH-1
    float run = 0.f;
    size_t idx = tid;
    g_P[idx] = 0.f;
    #pragma unroll 4
    for (int t = 1; t <= T_; ++t) {
        idx += BH;
        run += g_P[idx];
        g_P[idx] = run;
    }
}

// ---------------------------------------------------------------------------
// Kernel 3: the SNN.  grid = 128 t-values x 16 batch-tiles of 64 rows.
// 512 threads, 4x4 micro-tile, cols strided by 32.  State in registers.
// ---------------------------------------------------------------------------
__global__ void __launch_bounds__(512, 1)
k_snn(const float* __restrict__ Wh0, const float* __restrict__ Wout,
      const float* __restrict__ vx, const float* __restrict__ vy,
      float* __restrict__ out) {
    extern __shared__ float sm[];
    float* Wt     = sm;                      // [128][129]  Wt[k*129+h'] = Wh0[h'][k]
    float* spk    = Wt + 128 * 129;          // [64][128]
    float* WoutS  = spk + 64 * 128;          // [128][2]    WoutS[h*2+o] = Wout[o][h]
    float* memout = WoutS + 256;             // [64][2]

    const int tid = threadIdx.x;
    const int t   = blockIdx.x >> 4;
    const int b0  = (blockIdx.x & 15) * 64;

    for (int idx = tid; idx < H_ * H_; idx += 512) {
        int hp = idx >> 7, k = idx & 127;
        Wt[k * 129 + hp] = Wh0[idx];         // coalesced read, conflict-free store
    }
    if (tid < 256) WoutS[(tid & 127) * 2 + (tid >> 7)] = Wout[tid];
    if (tid < 128) memout[tid] = 0.f;
    __syncthreads();

    const int tx = tid & 31, ty = tid >> 5;
    const int r0 = ty * 4;
    float mem1[4][4] = {};
    float mem2[4][4] = {};

    for (int s = 0; s < 7; ++s) {
        // ---- window bounds (prefix-difference indices), uniform per block ----
        int lo, hi;
        if (t >= 49) {
            lo = t - 49 + 7 * s;
            hi = lo + 7;
        } else {
            int j0 = 7 * s; if (j0 < 1) j0 = 1;
            int j1 = 7 * s + 6; if (j1 > t + 1) j1 = t + 1;
            lo = j0 - 1;
            hi = (j1 >= j0) ? j1 : lo;       // empty window -> acc = 0
        }
        const float* __restrict__ Phi = g_P + (size_t)hi * BH;
        const float* __restrict__ Plo = g_P + (size_t)lo * BH;

        // ---- layer 1: leaky integrate, reset-to-zero, spike ----
        #pragma unroll
        for (int i = 0; i < 4; ++i) {
            const int b = b0 + r0 + i;
            #pragma unroll
            for (int j = 0; j < 4; ++j) {
                const int h = tx + 32 * j;
                float cur = Phi[(size_t)b * H_ + h] - Plo[(size_t)b * H_ + h];
                float m  = mem1[i][j];
                float nm = (m > THRESH) ? 0.f : fmaf(BETA, m, cur);
                mem1[i][j] = nm;
                spk[(r0 + i) * 128 + h] = (nm > THRESH) ? 1.f : 0.f;
            }
        }
        __syncthreads();

        // ---- hidden GEMM: cur2 = spk1 @ Wh0^T  (64x128 @ 128x128 tile) ----
        float acc[4][4] = {};
        #pragma unroll 4
        for (int k = 0; k < 128; ++k) {
            float a[4];
            #pragma unroll
            for (int i = 0; i < 4; ++i) a[i] = spk[(r0 + i) * 128 + k];  // broadcast
            #pragma unroll
            for (int j = 0; j < 4; ++j) {
                float w = Wt[k * 129 + tx + 32 * j];                     // conflict-free
                #pragma unroll
                for (int i = 0; i < 4; ++i) acc[i][j] += a[i] * w;
            }
        }
        __syncthreads();   // before overwriting spk with layer-2 spikes

        // ---- layer 2 ----
        #pragma unroll
        for (int i = 0; i < 4; ++i)
            #pragma unroll
            for (int j = 0; j < 4; ++j) {
                float m  = mem2[i][j];
                float nm = (m > THRESH) ? 0.f : fmaf(BETA, m, acc[i][j]);
                mem2[i][j] = nm;
                spk[(r0 + i) * 128 + tx + 32 * j] = (nm > THRESH) ? 1.f : 0.f;
            }
        __syncthreads();

        // ---- output projection + mem_out accumulate (no reset) ----
        if (tid < 256) {
            const int r = tid >> 2, p = tid & 3;
            float s0 = 0.f, s1 = 0.f;
            #pragma unroll 4
            for (int kk = 0; kk < 32; ++kk) {
                int k = p * 32 + ((kk + tx) & 31);      // lane-rotated -> conflict-free
                float v = spk[r * 128 + k];
                s0 = fmaf(v, WoutS[k * 2 + 0], s0);
                s1 = fmaf(v, WoutS[k * 2 + 1], s1);
            }
            s0 += __shfl_down_sync(0xffffffffu, s0, 2);
            s0 += __shfl_down_sync(0xffffffffu, s0, 1);
            s1 += __shfl_down_sync(0xffffffffu, s1, 2);
            s1 += __shfl_down_sync(0xffffffffu, s1, 1);
            if (p == 0) {
                memout[r * 2 + 0] = fmaf(BETA, memout[r * 2 + 0], s0);
                memout[r * 2 + 1] = fmaf(BETA, memout[r * 2 + 1], s1);
            }
        }
        __syncthreads();   // protect spk + memout before next step
    }

    // ---- epilogue: preds = mem_out * [v_x, v_y] ----
    if (tid < 128) {
        const int r = tid >> 1, o = tid & 1;
        const float v = (o == 0) ? vx[0] : vy[0];
        out[((size_t)t * B_ + b0 + r) * 2 + o] = memout[r * 2 + o] * v;
    }
}

// ---------------------------------------------------------------------------
extern "C" void kernel_launch(void* const* d_in, const int* in_sizes, int n_in,
                              void* d_out, int out_size) {
    const float* x    = (const float*)d_in[0];
    const float* Win  = (const float*)d_in[1];
    const float* Wh0  = (const float*)d_in[2];
    const float* Wout = (const float*)d_in[3];
    const float* vx   = (const float*)d_in[4];
    const float* vy   = (const float*)d_in[5];
    float* out = (float*)d_out;

    const int smem1 = (96 * 129 + 64 * 96) * 4;                 // 74112 B
    const int smem3 = (128 * 129 + 64 * 128 + 256 + 128) * 4;   // 100352 B
    cudaFuncSetAttribute(k_gemm_in, cudaFuncAttributeMaxDynamicSharedMemorySize, smem1);
    cudaFuncSetAttribute(k_snn,     cudaFuncAttributeMaxDynamicSharedMemorySize, smem3);

    k_gemm_in<<<(T_ * B_) / 64, 512, smem1>>>(x, Win);
    k_prefix<<<BH / 256, 256>>>();
    k_snn<<<T_ * 16, 512, smem3>>>(Wh0, Wout, vx, vy, out);
}

// round 5
// speedup vs baseline: 1.5378x; 1.5326x over previous
#include <cuda_runtime.h>
#include <cuda_bf16.h>
#include <stdint.h>

#define T_  128
#define B_  1024
#define D_  96
#define H_  128
#define BH  (B_ * H_)      // 131072
#define NSL 129

#define BETA   0.9f
#define THRESH 0.5f

// Prefix sums over time of C[t] = x_t @ W_in^T
__device__ float g_P[(size_t)NSL * BH];   // ~67.6 MB

// ---------------------------------------------------------------------------
// Kernel 1: C = X @ W_in^T  (unchanged from passing round)
// ---------------------------------------------------------------------------
__global__ void k_gemm_in(const float* __restrict__ x, const float* __restrict__ Win) {
    extern __shared__ float sm[];
    float* Ws = sm;                // [96][129]
    float* As = sm + 96 * 129;     // [64][96]
    const int tid  = threadIdx.x;
    const int row0 = blockIdx.x * 64;

    for (int idx = tid; idx < H_ * D_; idx += 512) {
        int h = idx / D_, k = idx - h * D_;
        Ws[k * 129 + h] = Win[idx];
    }
    for (int idx = tid; idx < 64 * D_; idx += 512)
        As[idx] = x[(size_t)row0 * D_ + idx];
    __syncthreads();

    const int tx = tid & 31, ty = tid >> 5;
    const int r0 = ty * 4;
    float acc[4][4] = {};
    #pragma unroll 2
    for (int k = 0; k < D_; ++k) {
        float a[4];
        #pragma unroll
        for (int i = 0; i < 4; ++i) a[i] = As[(r0 + i) * 96 + k];
        #pragma unroll
        for (int j = 0; j < 4; ++j) {
            float w = Ws[k * 129 + tx + 32 * j];
            #pragma unroll
            for (int i = 0; i < 4; ++i) acc[i][j] += a[i] * w;
        }
    }
    #pragma unroll
    for (int i = 0; i < 4; ++i)
        #pragma unroll
        for (int j = 0; j < 4; ++j)
            g_P[(size_t)BH + (size_t)(row0 + r0 + i) * H_ + tx + 32 * j] = acc[i][j];
}

// ---------------------------------------------------------------------------
// Kernel 2: in-place prefix sum over t (unchanged)
// ---------------------------------------------------------------------------
__global__ void k_prefix() {
    const size_t tid = (size_t)blockIdx.x * blockDim.x + threadIdx.x;
    float run = 0.f;
    size_t idx = tid;
    g_P[idx] = 0.f;
    #pragma unroll 4
    for (int t = 1; t <= T_; ++t) {
        idx += BH;
        run += g_P[idx];
        g_P[idx] = run;
    }
}

// ---------------------------------------------------------------------------
// Kernel 3: SNN with mma.sync (HMMA) tensor cores — valid on plain sm_103
// ---------------------------------------------------------------------------
#define SPK_STR  272                     // 128 bf16 + 8 pad  (16B-aligned rows)
#define W_BYTES  (128 * SPK_STR)         // 34816 per term
#define SM_SPK   0                       // spike tile          34816
#define SM_W     34816                   // 3 W terms          104448
#define SM_MEM1  139264                  // mem1 flat           65536
#define SM_WOUT  204800                  // Wout                 1024
#define SM_MOUT  205824                  // memout               1024
#define SM_SRED  206848                  // reduction            8192
#define SM_TOTAL 215040

__device__ __forceinline__ uint32_t s2u(const void* p) {
    uint32_t a;
    asm("{ .reg .u64 t; cvta.to.shared.u64 t, %1; cvt.u32.u64 %0, t; }"
        : "=r"(a) : "l"(p));
    return a;
}

__device__ __forceinline__ void ldm4(uint32_t* r, uint32_t addr) {
    asm volatile("ldmatrix.sync.aligned.m8n8.x4.shared.b16 {%0,%1,%2,%3}, [%4];"
        : "=r"(r[0]), "=r"(r[1]), "=r"(r[2]), "=r"(r[3]) : "r"(addr));
}

__device__ __forceinline__ void mma16816(float* d, const uint32_t* a,
                                         uint32_t b0, uint32_t b1) {
    asm volatile(
        "mma.sync.aligned.m16n8k16.row.col.f32.bf16.bf16.f32 "
        "{%0,%1,%2,%3}, {%4,%5,%6,%7}, {%8,%9}, {%0,%1,%2,%3};"
        : "+f"(d[0]), "+f"(d[1]), "+f"(d[2]), "+f"(d[3])
        : "r"(a[0]), "r"(a[1]), "r"(a[2]), "r"(a[3]), "r"(b0), "r"(b1));
}

__global__ void __launch_bounds__(512, 1)
k_snn_mma(const float* __restrict__ Wh0, const float* __restrict__ Wout,
          const float* __restrict__ vx, const float* __restrict__ vy,
          float* __restrict__ out)
{
    extern __shared__ char smc[];
    const uint32_t smb = s2u(smc);
    float* sWout  = (float*)(smc + SM_WOUT);   // [2][128]
    float* memout = (float*)(smc + SM_MOUT);   // [256]

    const int tid  = threadIdx.x;
    const int w    = tid >> 5;
    const int lane = tid & 31;
    const int mg   = w & 1;        // m-group: rows 64*mg .. +63
    const int ng   = w >> 1;       // n-group: cols 16*ng .. +15
    const int t    = blockIdx.x >> 3;
    const int b0   = (blockIdx.x & 7) << 7;

    // ---- 3-way bf16 split of Wh0 into padded smem tiles (lo, mid, hi) ----
    for (int idx = tid; idx < H_ * H_; idx += 512) {
        int n = idx >> 7, k = idx & 127;
        float wv = Wh0[idx];
        __nv_bfloat16 h = __float2bfloat16(wv);
        float r1 = wv - __bfloat162float(h);
        __nv_bfloat16 m = __float2bfloat16(r1);
        float r2 = r1 - __bfloat162float(m);
        __nv_bfloat16 l = __float2bfloat16(r2);
        int off = n * SPK_STR + k * 2;
        *(__nv_bfloat16*)(smc + SM_W + 0 * W_BYTES + off) = l;
        *(__nv_bfloat16*)(smc + SM_W + 1 * W_BYTES + off) = m;
        *(__nv_bfloat16*)(smc + SM_W + 2 * W_BYTES + off) = h;
    }
    if (tid < 256) { sWout[tid] = Wout[tid]; memout[tid] = 0.f; }
    {   // mem1 = 0 (per-thread flat layout: float2 slot i at (i*512+tid))
        const float2 z = make_float2(0.f, 0.f);
        #pragma unroll
        for (int i = 0; i < 16; ++i)
            *(float2*)(smc + SM_MEM1 + ((size_t)i * 512 + tid) * 8) = z;
    }
    __syncthreads();

    float mem2[4][2][4];
    #pragma unroll
    for (int mt = 0; mt < 4; ++mt)
        #pragma unroll
        for (int nt = 0; nt < 2; ++nt)
            #pragma unroll
            for (int e = 0; e < 4; ++e) mem2[mt][nt][e] = 0.f;

    const int r00 = 64 * mg + (lane >> 2);          // layer-1 base row
    const int cb  = 16 * ng + 2 * (lane & 3);       // layer-1 base col
    const uint32_t aLdBase = smb + SM_SPK + (64 * mg + (lane & 15)) * SPK_STR
                           + ((lane >> 4) << 4);
    const uint32_t bLdBase = smb + SM_W + (16 * ng + (lane & 15)) * SPK_STR
                           + ((lane >> 4) << 4);

    for (int s = 0; s < 7; ++s) {
        // ---- window bounds (identical to passing kernel) ----
        int lo_, hi_;
        if (t >= 49) { lo_ = t - 49 + 7 * s; hi_ = lo_ + 7; }
        else {
            int j0 = 7 * s; if (j0 < 1) j0 = 1;
            int j1 = 7 * s + 6; if (j1 > t + 1) j1 = t + 1;
            lo_ = j0 - 1;
            hi_ = (j1 >= j0) ? j1 : lo_;
        }
        const float* __restrict__ Phi = g_P + (size_t)hi_ * BH;
        const float* __restrict__ Plo = g_P + (size_t)lo_ * BH;

        // ---- layer 1: exact fp32, spikes -> bf16x2 into padded smem tile ----
        #pragma unroll
        for (int mt = 0; mt < 4; ++mt)
            #pragma unroll
            for (int nt = 0; nt < 2; ++nt)
                #pragma unroll
                for (int h = 0; h < 2; ++h) {
                    const int idx = mt * 4 + nt * 2 + h;
                    const int r = r00 + 16 * mt + 8 * h;
                    const int c = cb + 8 * nt;
                    const size_t o = (size_t)(b0 + r) * H_ + c;
                    float2 ph = *(const float2*)(Phi + o);
                    float2 pl = *(const float2*)(Plo + o);
                    float2* m1p = (float2*)(smc + SM_MEM1 + ((size_t)idx * 512 + tid) * 8);
                    float2 m1 = *m1p;
                    float nx = (m1.x > THRESH) ? 0.f : fmaf(BETA, m1.x, ph.x - pl.x);
                    float ny = (m1.y > THRESH) ? 0.f : fmaf(BETA, m1.y, ph.y - pl.y);
                    *m1p = make_float2(nx, ny);
                    uint32_t wbits = (nx > THRESH ? 0x3F80u : 0u)
                                   | (ny > THRESH ? 0x3F800000u : 0u);
                    *(uint32_t*)(smc + SM_SPK + r * SPK_STR + c * 2) = wbits;
                }
        __syncthreads();

        // ---- hidden GEMM: acc = spk @ (Wlo+Wmid+Whi)^T, K=384 via mma.sync ----
        float acc[4][2][4];
        #pragma unroll
        for (int mt = 0; mt < 4; ++mt)
            #pragma unroll
            for (int nt = 0; nt < 2; ++nt)
                #pragma unroll
                for (int e = 0; e < 4; ++e) acc[mt][nt][e] = 0.f;

        #pragma unroll
        for (int ks = 0; ks < 8; ++ks) {
            uint32_t a[4][4];
            #pragma unroll
            for (int mt = 0; mt < 4; ++mt)
                ldm4(a[mt], aLdBase + mt * (16 * SPK_STR) + ks * 32);
            #pragma unroll
            for (int term = 0; term < 3; ++term) {
                uint32_t b[4];
                ldm4(b, bLdBase + term * W_BYTES + ks * 32);
                #pragma unroll
                for (int mt = 0; mt < 4; ++mt) {
                    mma16816(acc[mt][0], a[mt], b[0], b[2]);
                    mma16816(acc[mt][1], a[mt], b[1], b[3]);
                }
            }
        }

        // ---- layer 2 + output projection partials ----
        float sred_p[4][2][2];
        #pragma unroll
        for (int mt = 0; mt < 4; ++mt)
            #pragma unroll
            for (int h = 0; h < 2; ++h)
                sred_p[mt][h][0] = sred_p[mt][h][1] = 0.f;

        #pragma unroll
        for (int nt = 0; nt < 2; ++nt) {
            const int c = cb + 8 * nt;
            const float2 w0 = *(const float2*)(sWout + c);
            const float2 w1 = *(const float2*)(sWout + 128 + c);
            #pragma unroll
            for (int mt = 0; mt < 4; ++mt)
                #pragma unroll
                for (int e = 0; e < 4; ++e) {
                    const int h = e >> 1;
                    float m  = mem2[mt][nt][e];
                    float nm = (m > THRESH) ? 0.f : fmaf(BETA, m, acc[mt][nt][e]);
                    mem2[mt][nt][e] = nm;
                    float sp = (nm > THRESH) ? 1.f : 0.f;
                    float wa = (e & 1) ? w0.y : w0.x;
                    float wb = (e & 1) ? w1.y : w1.x;
                    sred_p[mt][h][0] = fmaf(sp, wa, sred_p[mt][h][0]);
                    sred_p[mt][h][1] = fmaf(sp, wb, sred_p[mt][h][1]);
                }
        }
        // butterfly over the 4 lanes sharing each row
        #pragma unroll
        for (int mt = 0; mt < 4; ++mt)
            #pragma unroll
            for (int h = 0; h < 2; ++h)
                #pragma unroll
                for (int o = 0; o < 2; ++o) {
                    float v = sred_p[mt][h][o];
                    v += __shfl_xor_sync(0xffffffffu, v, 1);
                    v += __shfl_xor_sync(0xffffffffu, v, 2);
                    sred_p[mt][h][o] = v;
                }
        if ((lane & 3) == 0) {
            #pragma unroll
            for (int mt = 0; mt < 4; ++mt)
                #pragma unroll
                for (int h = 0; h < 2; ++h) {
                    const int row = r00 + 16 * mt + 8 * h;
                    *(float*)(smc + SM_SRED + ((row * 2 + 0) * 8 + ng) * 4) = sred_p[mt][h][0];
                    *(float*)(smc + SM_SRED + ((row * 2 + 1) * 8 + ng) * 4) = sred_p[mt][h][1];
                }
        }
        __syncthreads();
        if (tid < 256) {
            const float4 v0 = *(const float4*)(smc + SM_SRED + tid * 32);
            const float4 v1 = *(const float4*)(smc + SM_SRED + tid * 32 + 16);
            float sum = ((v0.x + v0.y) + (v0.z + v0.w))
                      + ((v1.x + v1.y) + (v1.z + v1.w));
            memout[tid] = fmaf(BETA, memout[tid], sum);
        }
        // next sred writes happen only after the next spk __syncthreads,
        // which the tid<256 readers must also reach -> no extra sync needed
    }

    // ---- epilogue ----
    if (tid < 256) {
        const int row = tid >> 1, o = tid & 1;
        const float v = o ? vy[0] : vx[0];
        out[((size_t)t * B_ + b0 + row) * 2 + o] = memout[tid] * v;
    }
}

// ---------------------------------------------------------------------------
extern "C" void kernel_launch(void* const* d_in, const int* in_sizes, int n_in,
                              void* d_out, int out_size) {
    const float* x    = (const float*)d_in[0];
    const float* Win  = (const float*)d_in[1];
    const float* Wh0  = (const float*)d_in[2];
    const float* Wout = (const float*)d_in[3];
    const float* vx   = (const float*)d_in[4];
    const float* vy   = (const float*)d_in[5];
    float* out = (float*)d_out;

    const int smem1 = (96 * 129 + 64 * 96) * 4;   // 74112 B
    cudaFuncSetAttribute(k_gemm_in, cudaFuncAttributeMaxDynamicSharedMemorySize, smem1);
    cudaFuncSetAttribute(k_snn_mma, cudaFuncAttributeMaxDynamicSharedMemorySize, SM_TOTAL);

    k_gemm_in<<<(T_ * B_) / 64, 512, smem1>>>(x, Win);
    k_prefix<<<BH / 256, 256>>>();
    k_snn_mma<<<T_ * 8, 512, SM_TOTAL>>>(Wh0, Wout, vx, vy, out);
}